// round 1
// baseline (speedup 1.0000x reference)
#include <cuda_runtime.h>

// Problem constants (fixed by the reference): N=65536, K=256, D=512, ALPHA=1.
#define D_DIM   512
#define K_CL    256
#define N_MAX   65536

// GEMM tiling
#define BM      64
#define BN      256      // full K per block -> in-block row normalization
#define BK      16
#define PITCH_A 66       // even pitch, 2*(..) mod 32 spreads banks -> conflict-free stores
#define PITCH_B 258

__device__ float g_x2[N_MAX];
__device__ float g_c2[K_CL];

// ---- packed f32x2 helpers (Blackwell) ----
__device__ __forceinline__ unsigned long long pk2(float lo, float hi) {
    unsigned long long r;
    asm("mov.b64 %0, {%1, %2};" : "=l"(r) : "f"(lo), "f"(hi));
    return r;
}
__device__ __forceinline__ void unpk2(unsigned long long v, float& lo, float& hi) {
    asm("mov.b64 {%0, %1}, %2;" : "=f"(lo), "=f"(hi) : "l"(v));
}
__device__ __forceinline__ void fma2(unsigned long long& d, unsigned long long a,
                                     unsigned long long b) {
    asm("fma.rn.f32x2 %0, %1, %2, %0;" : "+l"(d) : "l"(a), "l"(b));
}

// ---- squared row norms: one warp per row of a [rows, 512] matrix ----
__global__ void sqnorm_kernel(const float* __restrict__ M, float* __restrict__ out, int rows) {
    int row  = blockIdx.x * 8 + (threadIdx.x >> 5);
    int lane = threadIdx.x & 31;
    if (row >= rows) return;
    const float4* p = reinterpret_cast<const float4*>(M) + (size_t)row * (D_DIM / 4);
    float s = 0.f;
#pragma unroll
    for (int i = 0; i < D_DIM / 128; i++) {
        float4 v = p[lane + 32 * i];
        s += v.x * v.x + v.y * v.y + v.z * v.z + v.w * v.w;
    }
#pragma unroll
    for (int o = 16; o; o >>= 1) s += __shfl_xor_sync(0xffffffffu, s, o);
    if (lane == 0) out[row] = s;
}

// ---- fused GEMM + soft-assignment epilogue ----
// C[n,k] tile computed as X[64,512] @ clusters[256,512]^T with BK=16 k-tiles.
// Thread (trow=tid/32, tcol=tid%32): 8 rows x 4 col-pairs (f32x2 accumulators).
// Warp w owns rows [trow*8, trow*8+8) across ALL 256 cols -> warp shfl row-sum.
__global__ __launch_bounds__(256, 2)
void gemm_q_kernel(const float* __restrict__ X, const float* __restrict__ C,
                   const float* __restrict__ x2, const float* __restrict__ c2,
                   float* __restrict__ out) {
    __shared__ float As[BK][PITCH_A];
    __shared__ float Bs[BK][PITCH_B];

    const int tid  = threadIdx.x;
    const int tcol = tid & 31;
    const int trow = tid >> 5;
    const int rowBase = blockIdx.x * BM;

    // global-load mapping: 1 float4 of X, 4 float4 of clusters per thread per tile
    const int am = tid >> 2;          // 0..63 (row within tile / cluster row group)
    const int ak = (tid & 3) * 4;     // 0,4,8,12 (k within BK)

    const float* Xp = X + (size_t)(rowBase + am) * D_DIM + ak;
    const float* Cp = C + (size_t)am * D_DIM + ak;

    unsigned long long acc[8][4];
#pragma unroll
    for (int ii = 0; ii < 8; ii++)
#pragma unroll
        for (int jj = 0; jj < 4; jj++) acc[ii][jj] = 0ull;

    // prefetch tile 0
    float4 pa = *reinterpret_cast<const float4*>(Xp);
    float4 pb[4];
#pragma unroll
    for (int t = 0; t < 4; t++)
        pb[t] = *reinterpret_cast<const float4*>(Cp + (size_t)t * 64 * D_DIM);

    const int NT = D_DIM / BK;  // 32 k-tiles
    for (int kt = 0; kt < NT; kt++) {
        __syncthreads();  // previous tile's compute done before overwrite
        // store A (transposed, conflict-free via pitch 66)
        As[ak + 0][am] = pa.x;
        As[ak + 1][am] = pa.y;
        As[ak + 2][am] = pa.z;
        As[ak + 3][am] = pa.w;
        // store B (transposed, conflict-free via pitch 258)
#pragma unroll
        for (int t = 0; t < 4; t++) {
            Bs[ak + 0][am + 64 * t] = pb[t].x;
            Bs[ak + 1][am + 64 * t] = pb[t].y;
            Bs[ak + 2][am + 64 * t] = pb[t].z;
            Bs[ak + 3][am + 64 * t] = pb[t].w;
        }
        __syncthreads();

        // prefetch next tile into registers (hides gmem latency under compute)
        if (kt + 1 < NT) {
            pa = *reinterpret_cast<const float4*>(Xp + (kt + 1) * BK);
#pragma unroll
            for (int t = 0; t < 4; t++)
                pb[t] = *reinterpret_cast<const float4*>(Cp + (size_t)t * 64 * D_DIM +
                                                         (kt + 1) * BK);
        }

        // compute: packed f32x2 outer product
#pragma unroll
        for (int kk = 0; kk < BK; kk++) {
            unsigned long long b2[4], a2[8];
#pragma unroll
            for (int jj = 0; jj < 4; jj++) {
                float2 b = *reinterpret_cast<const float2*>(&Bs[kk][2 * tcol + 64 * jj]);
                b2[jj] = pk2(b.x, b.y);
            }
#pragma unroll
            for (int ii = 0; ii < 8; ii++) {
                float a = As[kk][trow * 8 + ii];   // warp-broadcast
                a2[ii] = pk2(a, a);
            }
#pragma unroll
            for (int ii = 0; ii < 8; ii++)
#pragma unroll
                for (int jj = 0; jj < 4; jj++) fma2(acc[ii][jj], a2[ii], b2[jj]);
        }
    }

    // ---- epilogue: q = 1/(1+dist), row-normalize within warp ----
    const int row0 = rowBase + trow * 8;
    float2 cc[4];
#pragma unroll
    for (int jj = 0; jj < 4; jj++)
        cc[jj] = *reinterpret_cast<const float2*>(&c2[2 * tcol + 64 * jj]);

    float rsum[8];
#pragma unroll
    for (int ii = 0; ii < 8; ii++) {
        float xr = x2[row0 + ii];
        float s = 0.f;
#pragma unroll
        for (int jj = 0; jj < 4; jj++) {
            float lo, hi;
            unpk2(acc[ii][jj], lo, hi);
            float d0 = fmaxf(xr + cc[jj].x - 2.f * lo, 0.f);
            float d1 = fmaxf(xr + cc[jj].y - 2.f * hi, 0.f);
            float q0 = 1.f / (1.f + d0);   // ALPHA=1 -> exponent (a+1)/2 = 1
            float q1 = 1.f / (1.f + d1);
            s += q0 + q1;
            acc[ii][jj] = pk2(q0, q1);     // reuse accumulator registers
        }
        rsum[ii] = s;
    }

#pragma unroll
    for (int ii = 0; ii < 8; ii++) {
        float s = rsum[ii];
#pragma unroll
        for (int o = 16; o; o >>= 1) s += __shfl_xor_sync(0xffffffffu, s, o);
        float inv = 1.f / s;
        float* orow = out + (size_t)(row0 + ii) * K_CL;
#pragma unroll
        for (int jj = 0; jj < 4; jj++) {
            float lo, hi;
            unpk2(acc[ii][jj], lo, hi);
            float2 v;
            v.x = lo * inv;
            v.y = hi * inv;
            *reinterpret_cast<float2*>(&orow[2 * tcol + 64 * jj]) = v;
        }
    }
}

extern "C" void kernel_launch(void* const* d_in, const int* in_sizes, int n_in,
                              void* d_out, int out_size) {
    const float* X = (const float*)d_in[0];   // [N, 512]
    const float* C = (const float*)d_in[1];   // [256, 512]
    float* out     = (float*)d_out;           // [N, 256]
    const int n = in_sizes[0] / D_DIM;

    float *px2 = nullptr, *pc2 = nullptr;
    cudaGetSymbolAddress((void**)&px2, g_x2);
    cudaGetSymbolAddress((void**)&pc2, g_c2);

    sqnorm_kernel<<<(n + 7) / 8, 256>>>(X, px2, n);
    sqnorm_kernel<<<(K_CL + 7) / 8, 256>>>(C, pc2, K_CL);
    gemm_q_kernel<<<n / BM, 256>>>(X, C, px2, pc2, out);
}

// round 3
// speedup vs baseline: 4.4403x; 4.4403x over previous
#include <cuda_runtime.h>
#include <cuda_bf16.h>
#include <cstdint>

// N=65536, K=256, D=512, ALPHA=1, fp32 in/out.
#define D_DIM  512
#define K_CL   256
#define BM     64
#define KC     64
#define NCHUNK 8
#define CB_CHUNK_BYTES (K_CL * KC * 2)   // 32768

// smem byte offsets
#define OFF_A0   0        // 64 x 128B  = 8192
#define OFF_A1   8192
#define OFF_B0   16384    // 256 x 128B = 32768
#define OFF_B1   49152
#define OFF_C2S  81920    // 256 f32
#define OFF_X2S  82944    // 64 f32
#define OFF_PART 83200    // 64*4 f32
#define OFF_INV  87296    // 64 f32
#define SMEM_TOTAL 87552
#define STAGE_PITCH 264   // stage: 64*264*4 = 67584 bytes, reuses [0,67584)

__device__ __align__(16) unsigned char g_cb[NCHUNK * CB_CHUNK_BYTES]; // 256KB bf16 swizzled
__device__ float g_c2[K_CL];

__device__ __forceinline__ uint32_t sw128(uint32_t off) { return off ^ ((off >> 3) & 0x70); }

__device__ __forceinline__ uint32_t smem_u32(const void* p) {
    uint32_t a;
    asm("{ .reg .u64 t; cvta.to.shared.u64 t, %1; cvt.u32.u64 %0, t; }" : "=r"(a) : "l"(p));
    return a;
}
__device__ __forceinline__ float frcp(float x) {
    float r; asm("rcp.approx.f32 %0, %1;" : "=f"(r) : "f"(x)); return r;
}
__device__ __forceinline__ void ldsm_x4(uint32_t (&r)[4], uint32_t addr) {
    asm volatile("ldmatrix.sync.aligned.m8n8.x4.shared.b16 {%0,%1,%2,%3}, [%4];"
                 : "=r"(r[0]), "=r"(r[1]), "=r"(r[2]), "=r"(r[3]) : "r"(addr));
}
__device__ __forceinline__ void mma16816(float (&d)[4], const uint32_t (&a)[4],
                                         uint32_t b0, uint32_t b1) {
    asm volatile("mma.sync.aligned.m16n8k16.row.col.f32.bf16.bf16.f32 "
                 "{%0,%1,%2,%3}, {%4,%5,%6,%7}, {%8,%9}, {%0,%1,%2,%3};"
                 : "+f"(d[0]), "+f"(d[1]), "+f"(d[2]), "+f"(d[3])
                 : "r"(a[0]), "r"(a[1]), "r"(a[2]), "r"(a[3]), "r"(b0), "r"(b1));
}
#define CP_ASYNC16(dst, src) \
    asm volatile("cp.async.cg.shared.global [%0], [%1], 16;" :: "r"(dst), "l"(src) : "memory")
#define CP_COMMIT() asm volatile("cp.async.commit_group;" ::: "memory")
#define CP_WAIT0()  asm volatile("cp.async.wait_group 0;" ::: "memory")

// ---- prepass: clusters fp32 -> bf16 chunk-blocked + SW128-swizzled, plus c2 norms ----
__global__ void prep_c_kernel(const float* __restrict__ C) {
    int w = (blockIdx.x * blockDim.x + threadIdx.x) >> 5;  // one warp per cluster row
    int lane = threadIdx.x & 31;
    if (w >= K_CL) return;
    const float4* src = reinterpret_cast<const float4*>(C + (size_t)w * D_DIM);
    float s = 0.f;
#pragma unroll
    for (int i = 0; i < 4; i++) {
        int f4 = lane + 32 * i;                 // float4 index 0..127
        float4 v = src[f4];
        s += v.x * v.x + v.y * v.y + v.z * v.z + v.w * v.w;
        __nv_bfloat162 h0 = __float22bfloat162_rn(make_float2(v.x, v.y));
        __nv_bfloat162 h1 = __float22bfloat162_rn(make_float2(v.z, v.w));
        int col = f4 * 4;
        int chunk = col >> 6, kin = col & 63;
        uint32_t off = (uint32_t)chunk * CB_CHUNK_BYTES + sw128((uint32_t)w * 128 + kin * 2);
        uint2 pk = make_uint2(*(uint32_t*)&h0, *(uint32_t*)&h1);
        *reinterpret_cast<uint2*>(g_cb + off) = pk;
    }
#pragma unroll
    for (int o = 16; o; o >>= 1) s += __shfl_xor_sync(0xffffffffu, s, o);
    if (lane == 0) g_c2[w] = s;
}

// ---- main fused kernel ----
extern __shared__ char smem[];

__global__ __launch_bounds__(256, 2)
void cluster_q_kernel(const float* __restrict__ X, float* __restrict__ out) {
    const int tid = threadIdx.x;
    const int lane = tid & 31;
    const int w = tid >> 5, wm = w >> 2, wn = w & 3;
    const int rowBase = blockIdx.x * BM;
    const uint32_t sb = smem_u32(smem);

    ((float*)(smem + OFF_C2S))[tid] = g_c2[tid];

    // A-load mapping: thread -> row ar, float4 base af; 4 float4/chunk
    const int ar = tid >> 2;
    const int af = tid & 3;
    const float4* Xg = reinterpret_cast<const float4*>(X + (size_t)(rowBase + ar) * D_DIM) + af;

    float acc[2][8][4];
#pragma unroll
    for (int a = 0; a < 2; a++)
#pragma unroll
        for (int b = 0; b < 8; b++)
#pragma unroll
            for (int c = 0; c < 4; c++) acc[a][b][c] = 0.f;
    float rsx = 0.f;
    float4 xv[4];

    auto issueB = [&](int chunk, uint32_t bufoff) {
        const unsigned char* src = g_cb + (size_t)chunk * CB_CHUNK_BYTES;
#pragma unroll
        for (int i = 0; i < 8; i++) {
            uint32_t u = tid + 256 * i;
            CP_ASYNC16(sb + bufoff + u * 16, src + u * 16);
        }
    };
    auto loadX = [&](int chunk) {
#pragma unroll
        for (int i = 0; i < 4; i++) xv[i] = Xg[chunk * 16 + 4 * i];
    };
    auto storeA = [&](uint32_t bufoff) {
#pragma unroll
        for (int i = 0; i < 4; i++) {
            float4 v = xv[i];
            rsx = fmaf(v.x, v.x, fmaf(v.y, v.y, fmaf(v.z, v.z, fmaf(v.w, v.w, rsx))));
            __nv_bfloat162 h0 = __float22bfloat162_rn(make_float2(v.x, v.y));
            __nv_bfloat162 h1 = __float22bfloat162_rn(make_float2(v.z, v.w));
            uint32_t off = sw128((uint32_t)ar * 128 + (af + 4 * i) * 8);
            *reinterpret_cast<uint2*>(smem + bufoff + off) =
                make_uint2(*(uint32_t*)&h0, *(uint32_t*)&h1);
        }
    };
    auto mmaChunk = [&](uint32_t aoff, uint32_t boff) {
#pragma unroll
        for (int ks = 0; ks < 4; ks++) {
            const uint32_t kb = ks * 32;
            uint32_t afr[2][4];
#pragma unroll
            for (int mi = 0; mi < 2; mi++) {
                int row = wm * 32 + mi * 16 + ((lane >> 3) & 1) * 8 + (lane & 7);
                uint32_t kbyte = kb + (lane >> 4) * 16;
                ldsm_x4(afr[mi], sb + aoff + sw128((uint32_t)row * 128 + kbyte));
            }
#pragma unroll
            for (int nt = 0; nt < 4; nt++) {
                uint32_t bfr[4];
                int nrow = wn * 64 + nt * 16 + ((lane >> 4) & 1) * 8 + (lane & 7);
                uint32_t kbyte = kb + ((lane >> 3) & 1) * 16;
                ldsm_x4(bfr, sb + boff + sw128((uint32_t)nrow * 128 + kbyte));
#pragma unroll
                for (int mi = 0; mi < 2; mi++) {
                    mma16816(acc[mi][2 * nt], afr[mi], bfr[0], bfr[1]);
                    mma16816(acc[mi][2 * nt + 1], afr[mi], bfr[2], bfr[3]);
                }
            }
        }
    };

    // pipeline
    issueB(0, OFF_B0);
    CP_COMMIT();
    loadX(0);
    CP_WAIT0();
    storeA(OFF_A0);
    __syncthreads();
    for (int chunk = 0; chunk < NCHUNK; chunk++) {
        const uint32_t ao = (chunk & 1) ? OFF_A1 : OFF_A0;
        const uint32_t bo = (chunk & 1) ? OFF_B1 : OFF_B0;
        const uint32_t ano = (chunk & 1) ? OFF_A0 : OFF_A1;
        const uint32_t bno = (chunk & 1) ? OFF_B0 : OFF_B1;
        if (chunk + 1 < NCHUNK) {
            issueB(chunk + 1, bno);
            CP_COMMIT();
            loadX(chunk + 1);
        }
        mmaChunk(ao, bo);
        if (chunk + 1 < NCHUNK) {
            CP_WAIT0();
            storeA(ano);
        }
        __syncthreads();
    }

    // x2 norms: 4 lanes share row ar
    rsx += __shfl_xor_sync(0xffffffffu, rsx, 1);
    rsx += __shfl_xor_sync(0xffffffffu, rsx, 2);
    float* x2s = (float*)(smem + OFF_X2S);
    if ((tid & 3) == 0) x2s[ar] = rsx;
    __syncthreads();

    // ---- epilogue: q + row sums + stage ----
    float* stage = (float*)smem;                  // [64][264]
    float* c2s = (float*)(smem + OFF_C2S);
    float* part = (float*)(smem + OFF_PART);      // [64][4] per-warp row partials... wait [64][16]? no [64][4]
    float* invs = (float*)(smem + OFF_INV);

#pragma unroll
    for (int mi = 0; mi < 2; mi++) {
        const int r0 = wm * 32 + mi * 16 + (lane >> 2);
        const float xr0 = x2s[r0];
        const float xr1 = x2s[r0 + 8];
        float p0 = 0.f, p1 = 0.f;
#pragma unroll
        for (int ni = 0; ni < 8; ni++) {
            const int col = wn * 64 + ni * 8 + 2 * (lane & 3);
            const float c20 = c2s[col], c21 = c2s[col + 1];
            float q00 = frcp(1.f + fmaxf(fmaf(-2.f, acc[mi][ni][0], xr0 + c20), 0.f));
            float q01 = frcp(1.f + fmaxf(fmaf(-2.f, acc[mi][ni][1], xr0 + c21), 0.f));
            float q10 = frcp(1.f + fmaxf(fmaf(-2.f, acc[mi][ni][2], xr1 + c20), 0.f));
            float q11 = frcp(1.f + fmaxf(fmaf(-2.f, acc[mi][ni][3], xr1 + c21), 0.f));
            p0 += q00 + q01;
            p1 += q10 + q11;
            *reinterpret_cast<float2*>(&stage[r0 * STAGE_PITCH + col]) = make_float2(q00, q01);
            *reinterpret_cast<float2*>(&stage[(r0 + 8) * STAGE_PITCH + col]) = make_float2(q10, q11);
        }
        p0 += __shfl_xor_sync(0xffffffffu, p0, 1);
        p0 += __shfl_xor_sync(0xffffffffu, p0, 2);
        p1 += __shfl_xor_sync(0xffffffffu, p1, 1);
        p1 += __shfl_xor_sync(0xffffffffu, p1, 2);
        if ((lane & 3) == 0) {
            part[r0 * 4 + wn] = p0;
            part[(r0 + 8) * 4 + wn] = p1;
        }
    }
    __syncthreads();
    if (tid < 64)
        invs[tid] = frcp(part[tid * 4] + part[tid * 4 + 1] + part[tid * 4 + 2] + part[tid * 4 + 3]);
    __syncthreads();

    // copy-out: row r = tid>>2, 16 float4 per thread, coalesced
    {
        const int r = tid >> 2;
        const float iv = invs[r];
        float* orow = out + (size_t)(rowBase + r) * K_CL;
#pragma unroll
        for (int i = 0; i < 16; i++) {
            const int c4 = (tid & 3) + 4 * i;
            float4 v = *reinterpret_cast<float4*>(&stage[r * STAGE_PITCH + 4 * c4]);
            v.x *= iv; v.y *= iv; v.z *= iv; v.w *= iv;
            *reinterpret_cast<float4*>(&orow[4 * c4]) = v;
        }
    }
}

extern "C" void kernel_launch(void* const* d_in, const int* in_sizes, int n_in,
                              void* d_out, int out_size) {
    const float* X = (const float*)d_in[0];   // [65536, 512]
    const float* C = (const float*)d_in[1];   // [256, 512]
    float* out = (float*)d_out;               // [65536, 256]
    const int n = in_sizes[0] / D_DIM;

    cudaFuncSetAttribute(cluster_q_kernel, cudaFuncAttributeMaxDynamicSharedMemorySize,
                         SMEM_TOTAL);
    prep_c_kernel<<<32, 256>>>(C);
    cluster_q_kernel<<<n / BM, 256, SMEM_TOTAL>>>(X, out);
}